// round 17
// baseline (speedup 1.0000x reference)
#include <cuda_runtime.h>
#include <cuda_fp16.h>
#include <cstdint>

// ============================================================================
// Problem constants
// ============================================================================
#define NROWS 16384
#define MCOLS 16384
#define DDIM  512

#define BLOCK_M 128                 // X rows per CTA
#define TILE_N  512                 // Y rows per CTA pass (8 warpN x 64)
#define NTILES  (MCOLS / TILE_N)    // 32
#define KCHUNK  16                  // K elems per per-warp B chunk
#define NUM_KC  (DDIM / KCHUNK)     // 32
#define NITER   (NTILES * NUM_KC)   // 1024 per-warp chunks
#define NTHREADS 512                // 16 warps: warpM = wid>>3, warpN = wid&7
                                    // warp tile 64x64; 4 warps per SMSP

// SMEM layout (bytes). A (fp16) padded to stride 520 (1040 B = 65x16, aligned
// + conflict-free: row offsets mod 128 step by 16).
// B: PER-WARP double-buffered slices: 64 rows x 16 K fp16 stored as 128
//    16B cells, cell(n,h) at index n*2 + (h ^ ((n>>2)&1))  (XOR half-swap):
//    packed 2048 B, every cell 16-aligned, ldmatrix phases conflict-free
//    (indices mod 8 = {0,2,4,6,1,3,5,7}).
#define SA 520
#define SLICE_BYTES 2048
#define A_BYTES     (BLOCK_M * SA * 2)          // 133120
#define SM_A    0
#define SM_B    (A_BYTES)                       // 16 warps x 2 stages x 2048
#define SM_X2   (SM_B + 16 * 2 * SLICE_BYTES)   // 198656: x2 per row (128 f32)
#define SM_RMIN (SM_X2 + 512)                   // row mins (128 f32)
#define SM_RED  (SM_RMIN + 512)                 // 16 f32
#define SM_FLAG (SM_RED + 64)                   // last-CTA flag
#define SMEM_TOTAL (SM_FLAG + 16)               // ~199 KB

// ============================================================================
// Device globals (no allocations allowed)
// ============================================================================
__device__ __half g_yh[(size_t)MCOLS * DDIM];
__device__ float g_c[MCOLS];
__device__ float g_psipart[MCOLS / 8];        // 2048 prep-block psi partials
__device__ float g_accpart[NROWS / BLOCK_M];  // 128 per-CTA row-sum partials
__device__ unsigned int g_done;               // ticket; reset by last CTA

// ============================================================================
// PTX helpers (sm_80-safe only: cp.async, ldmatrix, mma.sync)
// ============================================================================
__device__ __forceinline__ uint32_t smem_to_u32(const void* p) {
    uint32_t a;
    asm("{ .reg .u64 t; cvta.to.shared.u64 t, %1; cvt.u32.u64 %0, t; }" : "=r"(a) : "l"(p));
    return a;
}

__device__ __forceinline__ void cp16(uint32_t dst, const void* src) {
    asm volatile("cp.async.cg.shared.global [%0], [%1], 16;" :: "r"(dst), "l"(src) : "memory");
}
#define CP_COMMIT() asm volatile("cp.async.commit_group;" ::: "memory")
#define CP_WAIT(n)  asm volatile("cp.async.wait_group %0;" :: "n"(n) : "memory")

#define LDMX4(r0, r1, r2, r3, addr) \
    asm volatile("ldmatrix.sync.aligned.m8n8.x4.shared.b16 {%0,%1,%2,%3}, [%4];" \
        : "=r"(r0), "=r"(r1), "=r"(r2), "=r"(r3) : "r"(addr))

// fp16 inputs, fp16 accumulators: 2x rate vs f32-acc on the legacy HMMA path
#define MMAF16(d0, d1, a0, a1, a2, a3, b0, b1) \
    asm volatile("mma.sync.aligned.m16n8k16.row.col.f16.f16.f16.f16 " \
        "{%0,%1}, {%2,%3,%4,%5}, {%6,%7}, {%0,%1};" \
        : "+r"(d0), "+r"(d1) \
        : "r"(a0), "r"(a1), "r"(a2), "r"(a3), "r"(b0), "r"(b1))

__device__ __forceinline__ uint32_t pack_f16x2(float lo, float hi) {
    uint32_t u;
    asm("cvt.rn.f16x2.f32 %0, %1, %2;" : "=r"(u) : "f"(hi), "f"(lo));
    return u;
}

// ============================================================================
// Kernel: prep — Y -> fp16, c[m] = ||y_m||^2 - psi[m], per-block psi partials
// ============================================================================
__global__ void prep_kernel(const float* __restrict__ y, const float* __restrict__ psi) {
    __shared__ float spsi[8];
    int wid = threadIdx.x >> 5, lane = threadIdx.x & 31;
    int row = blockIdx.x * 8 + wid;
    const float4* yr = (const float4*)(y + (size_t)row * DDIM);
    uint32_t* yb = ((uint32_t*)g_yh) + (size_t)row * (DDIM / 2);
    float s = 0.f;
#pragma unroll
    for (int i = 0; i < 4; i++) {
        int idx = i * 32 + lane;
        float4 v = yr[idx];
        s += v.x * v.x + v.y * v.y + v.z * v.z + v.w * v.w;
        yb[idx * 2]     = pack_f16x2(v.x, v.y);
        yb[idx * 2 + 1] = pack_f16x2(v.z, v.w);
    }
#pragma unroll
    for (int o = 16; o; o >>= 1) s += __shfl_xor_sync(0xffffffffu, s, o);
    if (lane == 0) {
        float p = psi[row];
        g_c[row] = s - p;
        spsi[wid] = p;
    }
    __syncthreads();
    if (threadIdx.x == 0) {
        float ps = 0.f;
#pragma unroll
        for (int i = 0; i < 8; i++) ps += spsi[i];
        g_psipart[blockIdx.x] = ps;
    }
}

// ============================================================================
// Per-warp B chunk issue: this warp's 64 Y-rows x 16 K into its own slice.
// 128 x 16B cells, 4 per lane. lane: row = (lane>>1)+16j, khalf = lane&1.
// Cell index = row*2 + (khalf ^ ((row>>2)&1)); swap bit s is lane-constant:
// s = (lane&1) ^ ((lane>>3)&1)   (16j contributes 0 to bit2 of row).
// ============================================================================
__device__ __forceinline__ void issue_warp_chunk(
    uint32_t bwarp, int warpN, int i, int lane
) {
    int t = i >> 5, kc = i & 31, stg = i & 1;
    int row0 = lane >> 1;
    uint32_t s = (uint32_t)((lane & 1) ^ ((lane >> 3) & 1));
    const char* src = (const char*)g_yh +
        ((size_t)(t * TILE_N + warpN * 64 + row0) * DDIM
         + (size_t)kc * KCHUNK) * 2 + (lane & 1) * 16;
    uint32_t dst = bwarp + stg * SLICE_BYTES + (uint32_t)row0 * 32 + s * 16;
#pragma unroll
    for (int j = 0; j < 4; j++)
        cp16(dst + j * 512, src + (size_t)j * 16 * DDIM * 2);
}

// ============================================================================
// Main kernel: 128 CTAs x 512 threads (16 warps, 4 per SMSP).
// A (128x512 fp16) resident in SMEM. Each warp streams its own B slice
// (64 rows x 16 K, XOR half-swap layout) through a private 2-stage cp.async
// pipeline — NO cross-warp sync in the main loop. Warp tile 64x64, fp16
// accumulators (2x HMMA rate). Fused (c - 2*S) row-min epilogue.
// ============================================================================
__global__ void __launch_bounds__(NTHREADS, 1) semidual_main(
    const float* __restrict__ x, float* __restrict__ out
) {
    extern __shared__ char smem[];
    uint32_t sb = smem_to_u32(smem);
    int tid = threadIdx.x, lane = tid & 31, wid = tid >> 5;
    int warpM = wid >> 3, warpN = wid & 7;
    uint32_t bwarp = sb + SM_B + (uint32_t)wid * (2 * SLICE_BYTES);

    // -------- prologue: each warp starts its first B chunk --------
    issue_warp_chunk(bwarp, warpN, 0, lane);
    CP_COMMIT();

    // -------- load A rows, convert to fp16 (padded), compute x2 --------
    {
        int row = tid >> 2, q = tid & 3;   // 4 threads per row
        const float4* xr = (const float4*)(x + (size_t)(blockIdx.x * BLOCK_M + row) * DDIM
                                           + (size_t)q * 128);
        uint32_t* As = (uint32_t*)(smem + SM_A) + row * (SA / 2) + q * 64;
        float s = 0.f;
#pragma unroll
        for (int i = 0; i < 32; i++) {
            float4 v = xr[i];
            s += v.x * v.x + v.y * v.y + v.z * v.z + v.w * v.w;
            As[2 * i]     = pack_f16x2(v.x, v.y);
            As[2 * i + 1] = pack_f16x2(v.z, v.w);
        }
        s += __shfl_xor_sync(0xffffffffu, s, 1);
        s += __shfl_xor_sync(0xffffffffu, s, 2);
        if (q == 0) ((float*)(smem + SM_X2))[row] = s;
    }
    __syncthreads();   // A visible to all; last CTA-wide sync before tail

    // -------- ldmatrix base addresses --------
    // A fragment m16k16: lanes 0-15 -> rows, lanes 16-31 -> +16B (k8-15)
    uint32_t aBase0 = sb + SM_A +
        (uint32_t)(((warpM * 64 + (lane & 15)) * SA + (lane >> 4) * 8) * 2);
    // B lane mapping per LDMX4 (x4): r = (lane&7) + ((lane>>4)<<3) (row in
    // 16-group), h = (lane>>3)&1 (k-half). XOR half-swap uses bit2 of r,
    // which equals bit2 of lane. Cell offset = (r*2 + (h ^ b2)) * 16.
    uint32_t bOff;
    {
        uint32_t r = (uint32_t)((lane & 7) + ((lane >> 4) << 3));
        uint32_t h = (uint32_t)((lane >> 3) & 1);
        uint32_t b2 = (uint32_t)((lane >> 2) & 1);
        bOff = (r * 2 + (h ^ b2)) * 16;
    }

    uint32_t acc[4][8][2];   // fp16x2 accumulators, 64x64 warp tile
    float rmin[4][2] = {{3.0e38f, 3.0e38f}, {3.0e38f, 3.0e38f},
                        {3.0e38f, 3.0e38f}, {3.0e38f, 3.0e38f}};

    // -------- main loop: per-warp pipeline, NO cross-warp sync --------
    for (int i = 0; i < NITER; i++) {
        int kc = i & 31, stg = i & 1;

        // issue chunk i+1 into other stage (freed by chunk i-1, program
        // order), then wait until chunk i is resident.
        if (i + 1 < NITER) {
            issue_warp_chunk(bwarp, warpN, i + 1, lane);
            CP_COMMIT();
            CP_WAIT(1);
        } else {
            CP_WAIT(0);
        }
        __syncwarp();

        if (kc == 0) {
#pragma unroll
            for (int mt = 0; mt < 4; mt++)
#pragma unroll
                for (int nb = 0; nb < 8; nb++) {
                    acc[mt][nb][0] = 0u;
                    acc[mt][nb][1] = 0u;
                }
        }

        uint32_t bstage = bwarp + stg * SLICE_BYTES + bOff;
        uint32_t koffA = (uint32_t)kc * (KCHUNK * 2);

        // ---- one k=16 step: 8 LDSM, 32 MMA (fp16 acc) ----
        uint32_t af[4][4], bf[8][2];
#pragma unroll
        for (int mt = 0; mt < 4; mt++)
            LDMX4(af[mt][0], af[mt][1], af[mt][2], af[mt][3],
                  aBase0 + (uint32_t)(mt * 16 * SA * 2) + koffA);
#pragma unroll
        for (int nb2 = 0; nb2 < 4; nb2++)
            LDMX4(bf[2 * nb2][0], bf[2 * nb2][1],
                  bf[2 * nb2 + 1][0], bf[2 * nb2 + 1][1],
                  bstage + (uint32_t)(nb2 * 512));   // 16 rows = 32 cells = 512 B
#pragma unroll
        for (int mt = 0; mt < 4; mt++)
#pragma unroll
            for (int nb = 0; nb < 8; nb++)
                MMAF16(acc[mt][nb][0], acc[mt][nb][1],
                       af[mt][0], af[mt][1], af[mt][2], af[mt][3],
                       bf[nb][0], bf[nb][1]);

        if (kc == 31) {
            // epilogue: v = c - 2*S, fold into per-thread row mins.
            int t = i >> 5;
            const float2* cg = (const float2*)(g_c + t * TILE_N + warpN * 64);
#pragma unroll
            for (int nb = 0; nb < 8; nb++) {
                float2 c2 = __ldg(cg + ((nb * 8 + (lane & 3) * 2) >> 1));
#pragma unroll
                for (int mt = 0; mt < 4; mt++) {
                    float2 v0 = __half22float2(
                        *reinterpret_cast<const __half2*>(&acc[mt][nb][0]));
                    float2 v1 = __half22float2(
                        *reinterpret_cast<const __half2*>(&acc[mt][nb][1]));
                    rmin[mt][0] = fminf(rmin[mt][0], fmaf(-2.f, v0.x, c2.x));
                    rmin[mt][0] = fminf(rmin[mt][0], fmaf(-2.f, v0.y, c2.y));
                    rmin[mt][1] = fminf(rmin[mt][1], fmaf(-2.f, v1.x, c2.x));
                    rmin[mt][1] = fminf(rmin[mt][1], fmaf(-2.f, v1.y, c2.y));
                }
            }
        }
    }

    // -------- per-row min across warps --------
    // quad reduce (lanes in a quad share the same rows, different cols)
#pragma unroll
    for (int mt = 0; mt < 4; mt++)
#pragma unroll
        for (int rh = 0; rh < 2; rh++) {
            float v = rmin[mt][rh];
            v = fminf(v, __shfl_xor_sync(0xffffffffu, v, 1));
            v = fminf(v, __shfl_xor_sync(0xffffffffu, v, 2));
            rmin[mt][rh] = v;
        }

    float* rowmin = (float*)(smem + SM_RMIN);
    int r0 = warpM * 64 + (lane >> 2);
    __syncthreads();
    if (warpN == 0 && (lane & 3) == 0) {
#pragma unroll
        for (int mt = 0; mt < 4; mt++) {
            rowmin[r0 + mt * 16]     = rmin[mt][0];
            rowmin[r0 + mt * 16 + 8] = rmin[mt][1];
        }
    }
#pragma unroll
    for (int wn = 1; wn < 8; wn++) {
        __syncthreads();
        if (warpN == wn && (lane & 3) == 0) {
#pragma unroll
            for (int mt = 0; mt < 4; mt++) {
                rowmin[r0 + mt * 16]     = fminf(rowmin[r0 + mt * 16],     rmin[mt][0]);
                rowmin[r0 + mt * 16 + 8] = fminf(rowmin[r0 + mt * 16 + 8], rmin[mt][1]);
            }
        }
    }
    __syncthreads();

    // -------- CTA row-sum partial --------
    float val = 0.f;
    if (tid < 128) val = ((float*)(smem + SM_X2))[tid] + rowmin[tid];
#pragma unroll
    for (int o = 16; o; o >>= 1) val += __shfl_xor_sync(0xffffffffu, val, o);
    float* red = (float*)(smem + SM_RED);
    if (lane == 0) red[wid] = val;
    __syncthreads();
    if (tid == 0) {
        float s = 0.f;
#pragma unroll
        for (int w = 0; w < 16; w++) s += red[w];
        g_accpart[blockIdx.x] = s;
        __threadfence();
        unsigned int old = atomicAdd(&g_done, 1u);
        *(int*)(smem + SM_FLAG) = (old == (unsigned int)(gridDim.x - 1)) ? 1 : 0;
    }
    __syncthreads();

    // -------- last-done CTA: reduce all partials, write output --------
    if (*(int*)(smem + SM_FLAG)) {
        float s = 0.f;
#pragma unroll
        for (int j = 0; j < MCOLS / 8 / NTHREADS; j++)
            s += g_psipart[tid + j * NTHREADS];
        if (tid < NROWS / BLOCK_M) s += g_accpart[tid];
#pragma unroll
        for (int o = 16; o; o >>= 1) s += __shfl_xor_sync(0xffffffffu, s, o);
        if (lane == 0) red[wid] = s;
        __syncthreads();
        if (tid == 0) {
            float tot = 0.f;
#pragma unroll
            for (int w = 0; w < 16; w++) tot += red[w];
            out[0] = tot * (1.0f / 16384.0f);
            g_done = 0;   // reset for next graph replay
        }
    }
}

// ============================================================================
// Host launch — 2 launches
// ============================================================================
extern "C" void kernel_launch(void* const* d_in, const int* in_sizes, int n_in,
                              void* d_out, int out_size) {
    const float* x   = (const float*)d_in[0];
    const float* y   = (const float*)d_in[1];
    const float* psi = (const float*)d_in[2];
    float* out = (float*)d_out;
    (void)in_sizes; (void)n_in; (void)out_size;

    cudaFuncSetAttribute(semidual_main, cudaFuncAttributeMaxDynamicSharedMemorySize,
                         SMEM_TOTAL);

    prep_kernel<<<MCOLS / 8, 256>>>(y, psi);
    semidual_main<<<NROWS / BLOCK_M, NTHREADS, SMEM_TOTAL>>>(x, out);
}